// round 16
// baseline (speedup 1.0000x reference)
#include <cuda_runtime.h>
#include <cuda_bf16.h>

// PMF: out[p] = relu(dot(user_emb[user_ids[p]], item_emb[item_ids[p]])), D=64 fp32.
//
// R16: test the within-LDG replay theory. All previous 90.6us kernels used
// 16-lane float4 gathers: each warp LDG.128 spans 4 distinct 128B lines ->
// 3 within-LDG replay wavefronts @2.07cyc each (B300: cross-LDG wf = 1.0cyc,
// within-LDG wf = 2.07cyc). Here: 32 lanes per pair, float2 per lane (LDG.64)
// -> one warp instruction = one full 256B row = 2 lines = only 1 replay.
// Same total wavefronts, ~15% less L1tex replay cost. Register pressure
// halves (4 regs/pair), so PB=8 fits in ~50 regs.
//   phase 1: 16 broadcast id loads (independent)
//   phase 2: 16 independent LDG.64 row loads (full warp per row)
//   phase 3: dot + 5-step 32-lane shfl reduction + store

#define HIDDEN 64
#define THREADS 256
#define WARPS (THREADS / 32)               // 8
#define PB 8                                // pairs per warp
#define PAIRS_PER_BLOCK (WARPS * PB)        // 64

__global__ __launch_bounds__(THREADS)
void pmf_kernel(const float* __restrict__ user_emb,
                const float* __restrict__ item_emb,
                const int*   __restrict__ user_ids,
                const int*   __restrict__ item_ids,
                float*       __restrict__ out,
                int num_pairs)
{
    const int warp = threadIdx.x >> 5;     // 0..7
    const int lane = threadIdx.x & 31;     // 0..31
    const int base = blockIdx.x * PAIRS_PER_BLOCK + warp;

    // Phase 1: id loads (broadcast within warp), independent, front-batched.
    int uid[PB], iid[PB];
    #pragma unroll
    for (int k = 0; k < PB; k++) {
        int p = base + k * WARPS;
        int q = (p < num_pairs) ? p : 0;
        uid[k] = __ldg(&user_ids[q]);
        iid[k] = __ldg(&item_ids[q]);
    }

    // Phase 2: all row loads, independent, front-batched (16 LDG.64/thread).
    // One warp instruction covers one whole 256B row (2 lines, 1 replay).
    float2 u[PB], v[PB];
    #pragma unroll
    for (int k = 0; k < PB; k++) {
        u[k] = __ldg(reinterpret_cast<const float2*>(
                   user_emb + (long long)uid[k] * HIDDEN) + lane);
        v[k] = __ldg(reinterpret_cast<const float2*>(
                   item_emb + (long long)iid[k] * HIDDEN) + lane);
    }

    // Phase 3: dot products, 32-lane reductions, stores.
    #pragma unroll
    for (int k = 0; k < PB; k++) {
        float acc = u[k].x * v[k].x + u[k].y * v[k].y;
        acc += __shfl_xor_sync(0xFFFFFFFFu, acc, 16);
        acc += __shfl_xor_sync(0xFFFFFFFFu, acc, 8);
        acc += __shfl_xor_sync(0xFFFFFFFFu, acc, 4);
        acc += __shfl_xor_sync(0xFFFFFFFFu, acc, 2);
        acc += __shfl_xor_sync(0xFFFFFFFFu, acc, 1);
        int p = base + k * WARPS;
        if (lane == 0 && p < num_pairs)
            out[p] = fmaxf(acc, 0.0f);
    }
}

extern "C" void kernel_launch(void* const* d_in, const int* in_sizes, int n_in,
                              void* d_out, int out_size)
{
    const float* user_emb = (const float*)d_in[0];
    const float* item_emb = (const float*)d_in[1];
    const int*   user_ids = (const int*)d_in[2];
    const int*   item_ids = (const int*)d_in[3];
    float*       out      = (float*)d_out;

    int num_pairs = in_sizes[2];
    int blocks = (num_pairs + PAIRS_PER_BLOCK - 1) / PAIRS_PER_BLOCK;

    pmf_kernel<<<blocks, THREADS>>>(user_emb, item_emb, user_ids, item_ids,
                                    out, num_pairs);
}

// round 17
// speedup vs baseline: 1.3283x; 1.3283x over previous
#include <cuda_runtime.h>
#include <cuda_bf16.h>

// PMF: out[p] = relu(dot(user_emb[user_ids[p]], item_emb[item_ids[p]])), D=64 fp32.
//
// FINAL = R4 (session best, 90.59us; reproduced 90.6/91.6 across reruns).
// The workload is floor-bound by L1tex/LSU service of its own gather demand:
// 2M pairs x 2 tables x 2 cache lines = 8M demand-line wavefronts, delivered
// via the minimum possible 2M LDG.128 row instructions. Probed and rejected:
//   - more in-flight work  (cp.async flat R7b, 3-stage pipeline R9): 90.6us
//   - fewer DRAM bytes     (two-pass user blocking R13): 90.6us/pass
//   - fewer L2 bytes       (bucketing R5/R6): preprocessing >> gain
//   - fewer lines/instr    (LDG.64 R16): 158us (L1 charges per instruction)
//
// Structure: 16 lanes per pair; each lane loads one float4 from the user row
// and one from the item row (two coalesced 128B lines per 256B row; LDG.128
// maximizes bytes per L1 issue slot). PB=8 pairs per group, ids then rows
// front-batched (16 independent LDG.128 per thread), 16-lane shfl_xor
// reduction, predicated store.

#define HIDDEN 64
#define THREADS 256
#define GROUPS_PER_BLOCK (THREADS / 16)            // 16
#define PB 8                                        // pairs per group
#define PAIRS_PER_BLOCK (GROUPS_PER_BLOCK * PB)     // 128

__global__ __launch_bounds__(THREADS, 3)
void pmf_kernel(const float* __restrict__ user_emb,
                const float* __restrict__ item_emb,
                const int*   __restrict__ user_ids,
                const int*   __restrict__ item_ids,
                float*       __restrict__ out,
                int num_pairs)
{
    const int group = threadIdx.x >> 4;    // 0..15
    const int lane  = threadIdx.x & 15;    // 0..15
    const int base  = blockIdx.x * PAIRS_PER_BLOCK + group;

    // Phase 1: all id loads, independent, front-batched.
    int uid[PB], iid[PB];
    #pragma unroll
    for (int k = 0; k < PB; k++) {
        int p = base + k * GROUPS_PER_BLOCK;
        int q = (p < num_pairs) ? p : 0;
        uid[k] = __ldg(&user_ids[q]);
        iid[k] = __ldg(&item_ids[q]);
    }

    // Phase 2: all row loads, independent, front-batched (16 LDG.128/thread).
    float4 u[PB], v[PB];
    #pragma unroll
    for (int k = 0; k < PB; k++) {
        u[k] = __ldg(reinterpret_cast<const float4*>(
                   user_emb + (long long)uid[k] * HIDDEN) + lane);
        v[k] = __ldg(reinterpret_cast<const float4*>(
                   item_emb + (long long)iid[k] * HIDDEN) + lane);
    }

    // Phase 3: dot products, 16-lane reductions, stores.
    #pragma unroll
    for (int k = 0; k < PB; k++) {
        float acc = u[k].x * v[k].x + u[k].y * v[k].y
                  + u[k].z * v[k].z + u[k].w * v[k].w;
        acc += __shfl_xor_sync(0xFFFFFFFFu, acc, 8);
        acc += __shfl_xor_sync(0xFFFFFFFFu, acc, 4);
        acc += __shfl_xor_sync(0xFFFFFFFFu, acc, 2);
        acc += __shfl_xor_sync(0xFFFFFFFFu, acc, 1);
        int p = base + k * GROUPS_PER_BLOCK;
        if (lane == 0 && p < num_pairs)
            out[p] = fmaxf(acc, 0.0f);
    }
}

extern "C" void kernel_launch(void* const* d_in, const int* in_sizes, int n_in,
                              void* d_out, int out_size)
{
    const float* user_emb = (const float*)d_in[0];
    const float* item_emb = (const float*)d_in[1];
    const int*   user_ids = (const int*)d_in[2];
    const int*   item_ids = (const int*)d_in[3];
    float*       out      = (float*)d_out;

    int num_pairs = in_sizes[2];
    int blocks = (num_pairs + PAIRS_PER_BLOCK - 1) / PAIRS_PER_BLOCK;

    pmf_kernel<<<blocks, THREADS>>>(user_emb, item_emb, user_ids, item_ids,
                                    out, num_pairs);
}